// round 8
// baseline (speedup 1.0000x reference)
#include <cuda_runtime.h>
#include <cuda_fp16.h>

#define DIM 300
#define C 16
#define NPTS 1048576u   // 2^20
#define PLANE (DIM * DIM)

// Pair-interleaved fp16 scratch (x-neighbor pre-clamped at build time).
// Plane block (o, y, x): 32 halves = 16 ch of __half2{ v[y][x], v[y][min(x+1,DIM-1)] }.
// Line  block (o, j):    32 halves = 16 ch of __half2{ v[j],    v[min(j+1,DIM-1)] }.
// o=0 -> (plane_yz, line_x), o=1 -> (plane_xz, line_y), o=2 -> (plane_xy, line_z)
__device__ __align__(128) __half g_plane_p[3 * PLANE * 2 * C];   // 17.28 MB
__device__ __align__(128) __half g_line_p[3 * DIM * 2 * C];      // 57.6 KB

__global__ void transpose_kernel(const float* __restrict__ pxy,
                                 const float* __restrict__ pyz,
                                 const float* __restrict__ pxz,
                                 const float* __restrict__ lx,
                                 const float* __restrict__ ly,
                                 const float* __restrict__ lz) {
    int id = blockIdx.x * blockDim.x + threadIdx.x;
    if (id < 3 * PLANE) {
        int p = id / PLANE;
        int pos = id - p * PLANE;       // y*DIM + x
        int x = pos % DIM;
        int dx = (x < DIM - 1) ? 1 : 0;
        const float* src = (p == 0) ? pyz : (p == 1) ? pxz : pxy;
        union { __half2 h2[16]; uint4 u[4]; } pk;
#pragma unroll
        for (int c = 0; c < C; c++) {
            float a = __ldg(&src[c * PLANE + pos]);
            float b = __ldg(&src[c * PLANE + pos + dx]);
            pk.h2[c] = __floats2half2_rn(a, b);
        }
        uint4* dst = reinterpret_cast<uint4*>(g_plane_p + (size_t)(p * PLANE + pos) * 2 * C);
#pragma unroll
        for (int j = 0; j < 4; j++) dst[j] = pk.u[j];
    } else if (id < 3 * PLANE + 3 * DIM) {
        int r = id - 3 * PLANE;
        int p = r / DIM;
        int pos = r - p * DIM;
        int dx = (pos < DIM - 1) ? 1 : 0;
        const float* src = (p == 0) ? lx : (p == 1) ? ly : lz;
        union { __half2 h2[16]; uint4 u[4]; } pk;
#pragma unroll
        for (int c = 0; c < C; c++) {
            float a = __ldg(&src[c * DIM + pos]);
            float b = __ldg(&src[c * DIM + pos + dx]);
            pk.h2[c] = __floats2half2_rn(a, b);
        }
        uint4* dst = reinterpret_cast<uint4*>(g_line_p + (size_t)(p * DIM + pos) * 2 * C);
#pragma unroll
        for (int j = 0; j < 4; j++) dst[j] = pk.u[j];
    }
}

// Decode one quarter-task into 32-bit uint4-element offsets + weights.
// No clamps: coords strictly in [-1,1) => x0,y0,j0 <= DIM-2 before +1; the x/j
// "+1" neighbor is pre-clamped inside the scratch block.
__device__ __forceinline__ void decode(unsigned id,
                                       const float2* __restrict__ coords_plane,
                                       const float2* __restrict__ coords_line,
                                       unsigned& poff, unsigned& loff,
                                       float& wx, float& wy, float& wl) {
    unsigned q = id & 3u;
    unsigned t = id >> 2;
    unsigned o = t >> 20;
    unsigned n = t & (NPTS - 1u);
    unsigned po = (o == 2u) ? 0u : o + 1u;

    float2 pc = __ldg(&coords_plane[po * NPTS + n]);
    float2 lc = __ldg(&coords_line[o * NPTS + n]);

    const float S = 0.5f * (DIM - 1);
    float ix = (pc.x + 1.0f) * S;
    float iy = (pc.y + 1.0f) * S;
    int x0 = (int)ix;                 // trunc == floor (ix >= 0)
    int y0 = (int)iy;
    wx = ix - (float)x0;
    wy = iy - (float)y0;
    poff = o * (unsigned)(PLANE * 4) + (unsigned)(y0 * DIM + x0) * 4u + q;

    float iyl = (lc.y + 1.0f) * S;
    int j0 = (int)iyl;
    wl = iyl - (float)j0;
    loff = o * (unsigned)(DIM * 4) + (unsigned)j0 * 4u + q;
}

__device__ __forceinline__ float4 combine(uint4 r0, uint4 r1, uint4 lr,
                                          float wx, float wy, float wl) {
    const __half2* h0 = reinterpret_cast<const __half2*>(&r0);
    const __half2* h1 = reinterpret_cast<const __half2*>(&r1);
    const __half2* hl = reinterpret_cast<const __half2*>(&lr);
    float res[4];
#pragma unroll
    for (int i = 0; i < 4; i++) {
        float2 f0 = __half22float2(h0[i]);   // (v[y0][x0], v[y0][x1])
        float2 f1 = __half22float2(h1[i]);   // (v[y1][x0], v[y1][x1])
        float2 fl2 = __half22float2(hl[i]);  // (l[j0], l[j1])
        float vx0 = fmaf(wx, f0.y - f0.x, f0.x);
        float vx1 = fmaf(wx, f1.y - f1.x, f1.x);
        float v   = fmaf(wy, vx1 - vx0, vx0);
        float lv  = fmaf(wl, fl2.y - fl2.x, fl2.x);
        res[i] = v * lv;
    }
    return make_float4(res[0], res[1], res[2], res[3]);
}

// 2 tasks per thread; all 6 texel loads issued before any unpack/FMA.
// 32-bit offsets into unified arrays keep per-task live state at 5 regs so
// 44 warps/SM fit (<=45 regs) -> ~264 in-flight loads/SM.
__global__ void __launch_bounds__(128, 11) sample_kernel(
    const float2* __restrict__ coords_plane,   // (3, N)
    const float2* __restrict__ coords_line,    // (3, N)
    float4* __restrict__ out)                  // (3, N, 4) float4
{
    unsigned base = blockIdx.x * 128u + threadIdx.x;   // < 3*N*2
    const unsigned HALF = 3u * NPTS * 2u;              // id stride between tasks

    unsigned pA, lA, pB, lB;
    float wxA, wyA, wlA, wxB, wyB, wlB;
    decode(base, coords_plane, coords_line, pA, lA, wxA, wyA, wlA);
    decode(base + HALF, coords_plane, coords_line, pB, lB, wxB, wyB, wlB);

    const uint4* P = reinterpret_cast<const uint4*>(g_plane_p);
    const uint4* L = reinterpret_cast<const uint4*>(g_line_p);

    // ---- issue all 6 texel loads (planes bypass L1; lines stay L1-hot) ----
    uint4 a0 = __ldcg(P + pA);
    uint4 a1 = __ldcg(P + pA + DIM * 4);
    uint4 b0 = __ldcg(P + pB);
    uint4 b1 = __ldcg(P + pB + DIM * 4);
    uint4 la = __ldg(L + lA);
    uint4 lb = __ldg(L + lB);

    // ---- compute + store ----
    __stcs(&out[base], combine(a0, a1, la, wxA, wyA, wlA));
    __stcs(&out[base + HALF], combine(b0, b1, lb, wxB, wyB, wlB));
}

extern "C" void kernel_launch(void* const* d_in, const int* in_sizes, int n_in,
                              void* d_out, int out_size) {
    const float* coords_plane = (const float*)d_in[0];
    const float* coords_line  = (const float*)d_in[1];
    const float* plane_xy     = (const float*)d_in[2];
    const float* plane_yz     = (const float*)d_in[3];
    const float* plane_xz     = (const float*)d_in[4];
    const float* line_x       = (const float*)d_in[5];
    const float* line_y       = (const float*)d_in[6];
    const float* line_z       = (const float*)d_in[7];
    float* out = (float*)d_out;

    {
        int total = 3 * PLANE + 3 * DIM;
        int block = 256;
        int grid = (total + block - 1) / block;
        transpose_kernel<<<grid, block>>>(plane_xy, plane_yz, plane_xz,
                                          line_x, line_y, line_z);
    }
    {
        unsigned threads_total = 3u * NPTS * 2u;   // 6,291,456
        int block = 128;
        int grid = (int)(threads_total / block);   // 49152
        sample_kernel<<<grid, block>>>(
            reinterpret_cast<const float2*>(coords_plane),
            reinterpret_cast<const float2*>(coords_line),
            reinterpret_cast<float4*>(out));
    }
}